// round 14
// baseline (speedup 1.0000x reference)
#include <cuda_runtime.h>
#include <cuda_bf16.h>
#include <cuda_fp16.h>
#include <cstdint>

#define BATCH 16
#define CIN   256
#define NPIX  4096   // 64*64
#define M3    768    // combined q,k,v output channels
#define KX    512    // x-split storage k length (hi 256 | lo 256)

// Scratch (device globals; no allocations allowed)
// g_qkvs: per (b, chan): [8KB fp16 hi plane | 8KB fp16 lo plane], NATURAL layout.
// lo planes are only written/read for the Q region (chan 0..255).
__device__ unsigned char g_qkvs[(size_t)BATCH * M3 * 16384];      // 201 MB
__device__ __half        g_xs [(size_t)BATCH * NPIX * KX];        // 67 MB  x split fp16, [b][p][kx]
__device__ __half        g_ws [(size_t)M3 * CIN];                 // 0.4 MB w_hi fp16, [o][c]

__device__ __forceinline__ uint32_t s2u(const void* p) {
    uint32_t a;
    asm("{ .reg .u64 t; cvta.to.shared.u64 t, %1; cvt.u32.u64 %0, t; }" : "=r"(a) : "l"(p));
    return a;
}

#define SWZ(off) ((off) ^ (((off) >> 3) & 0x70))

__device__ __forceinline__ void cp_async16(uint32_t dst, const void* src) {
    asm volatile("cp.async.cg.shared.global [%0], [%1], 16;" :: "r"(dst), "l"(src));
}

__device__ __forceinline__ void ldmatrix_x4(uint32_t* r, uint32_t addr) {
    asm volatile("ldmatrix.sync.aligned.m8n8.x4.shared.b16 {%0,%1,%2,%3}, [%4];"
                 : "=r"(r[0]), "=r"(r[1]), "=r"(r[2]), "=r"(r[3]) : "r"(addr));
}

__device__ __forceinline__ void ldmatrix_x4_trans(uint32_t* r, uint32_t addr) {
    asm volatile("ldmatrix.sync.aligned.m8n8.x4.trans.shared.b16 {%0,%1,%2,%3}, [%4];"
                 : "=r"(r[0]), "=r"(r[1]), "=r"(r[2]), "=r"(r[3]) : "r"(addr));
}

// fp16 mma
__device__ __forceinline__ void mma16816h(float* c, const uint32_t* a, uint32_t b0, uint32_t b1) {
    asm volatile(
        "mma.sync.aligned.m16n8k16.row.col.f32.f16.f16.f32 "
        "{%0,%1,%2,%3}, {%4,%5,%6,%7}, {%8,%9}, {%0,%1,%2,%3};"
        : "+f"(c[0]), "+f"(c[1]), "+f"(c[2]), "+f"(c[3])
        : "r"(a[0]), "r"(a[1]), "r"(a[2]), "r"(a[3]), "r"(b0), "r"(b1));
}

// Split v0,v1 into hi/lo fp16 pairs.
__device__ __forceinline__ void split_pair_h(float v0, float v1, uint32_t& hi, uint32_t& lo) {
    __half h0 = __float2half(v0);
    __half h1 = __float2half(v1);
    __half2 H; H.x = h0; H.y = h1;
    __half2 L;
    L.x = __float2half(v0 - __half2float(h0));
    L.y = __float2half(v1 - __half2float(h1));
    hi = *(uint32_t*)&H;
    lo = *(uint32_t*)&L;
}

// ---------------------------------------------------------------------------
// Kernel A: split x -> fp16 hi/lo, transposed to [b][p][kx] (kx: hi 0..255, lo 256..511)
// ---------------------------------------------------------------------------
__global__ __launch_bounds__(256) void split_x_kernel(const float* __restrict__ x) {
    __shared__ float s[64][65];
    const int b = blockIdx.z, c0 = blockIdx.y * 64, p0 = blockIdx.x * 64;
    const float* xb = x + ((size_t)b * CIN + c0) * NPIX + p0;
    const int t = threadIdx.x;
#pragma unroll
    for (int i = 0; i < 16; i++) {
        int idx = t + 256 * i;
        int c = idx >> 6, p = idx & 63;
        s[c][p] = xb[(size_t)c * NPIX + p];
    }
    __syncthreads();
    __half* xs = g_xs + ((size_t)b * NPIX + p0) * KX + c0;
#pragma unroll
    for (int i = 0; i < 16; i++) {
        int idx = t + 256 * i;
        int cc = idx & 63, p = idx >> 6;
        float v = s[cc][p];
        __half h = __float2half(v);
        __half l = __float2half(v - __half2float(h));
        xs[(size_t)p * KX + cc]       = h;
        xs[(size_t)p * KX + 256 + cc] = l;
    }
}

// ---------------------------------------------------------------------------
// Kernel B: w_hi fp16 only, [o][c]
// ---------------------------------------------------------------------------
__global__ __launch_bounds__(256) void split_w_kernel(
    const float* __restrict__ wq, const float* __restrict__ wk, const float* __restrict__ wv) {
    int idx = blockIdx.x * 256 + threadIdx.x;   // 768*256 total
    int o = idx >> 8, c = idx & 255;
    const float* w = (o < 256) ? wq : (o < 512) ? wk : wv;
    g_ws[idx] = __float2half(w[(o & 255) * CIN + c]);
}

// ---------------------------------------------------------------------------
// Kernel C: HMMA fp16 GEMM, K'=512, CTA tile 128x128, 128 threads.
// 4 warps in 2x2 grid, warp tile 64x64 (128 accums/thread).
// Operand smem traffic: A x2 + B x2 + stores = 96KB/stage (25% less than 4x2).
// ---------------------------------------------------------------------------
#define BM 128
#define BN 128
#define BK 64
#define NIT 8
#define STAGE_BYTES (BM * BK * 2 + BN * BK * 2)   // 32 KB (A then B)
#define NSTAGE 3

extern __shared__ __align__(1024) char dynsmem[];

__global__ __launch_bounds__(128) void qkv_mma_kernel(
    const float* __restrict__ bq, const float* __restrict__ bk, const float* __restrict__ bv)
{
    const int t    = threadIdx.x;
    const int lane = t & 31;
    const int warp = t >> 5;
    const int wm   = warp & 1;     // 2 warps along M: 64 rows each
    const int wn   = warp >> 1;    // 2 warps along N: 64 cols each

    const int b  = blockIdx.z;
    const int o0 = blockIdx.y * BM;
    const int p0 = blockIdx.x * BN;

    const uint32_t smemBase = s2u(dynsmem);

    const __half* Wb = g_ws + (size_t)o0 * CIN;
    const __half* Xb = g_xs + ((size_t)b * NPIX + p0) * KX;

    float c[4][8][4];
#pragma unroll
    for (int i = 0; i < 4; i++)
#pragma unroll
        for (int j = 0; j < 8; j++)
#pragma unroll
            for (int k = 0; k < 4; k++) c[i][j][k] = 0.f;

    auto load_stage = [&](int it) {
        const int ka = (it & 3) * BK;          // W region: hi reused for x_lo term
        const int kb = it * BK;                // X region: [hi | lo] straight through
        const uint32_t aB = smemBase + (it % NSTAGE) * STAGE_BYTES;
        const uint32_t bB = aB + BM * BK * 2;
#pragma unroll
        for (int j = 0; j < 8; j++) {          // A: 1024 chunks of 16B
            int idx = t + 128 * j;
            int row = idx >> 3, c16 = idx & 7;
            cp_async16(aB + SWZ(row * 128 + c16 * 16),
                       (const char*)(Wb + (size_t)row * CIN + ka) + c16 * 16);
        }
#pragma unroll
        for (int j = 0; j < 8; j++) {          // B: 1024 chunks of 16B
            int idx = t + 128 * j;
            int row = idx >> 3, c16 = idx & 7;
            cp_async16(bB + SWZ(row * 128 + c16 * 16),
                       (const char*)(Xb + (size_t)row * KX + kb) + c16 * 16);
        }
        asm volatile("cp.async.commit_group;");
    };

    auto compute_stage = [&](int it) {
        const uint32_t aB = smemBase + (it % NSTAGE) * STAGE_BYTES;
        const uint32_t bB = aB + BM * BK * 2;
#pragma unroll
        for (int ks = 0; ks < 4; ks++) {
            uint32_t af[4][4];
#pragma unroll
            for (int mt = 0; mt < 4; mt++) {
                int row = wm * 64 + mt * 16 + (lane & 15);
                int col = ks * 32 + (lane >> 4) * 16;
                ldmatrix_x4(af[mt], aB + SWZ(row * 128 + col));
            }
            uint32_t bf[4][4];
#pragma unroll
            for (int np = 0; np < 4; np++) {
                int row = wn * 64 + np * 16 + (lane & 7) + ((lane >> 4) << 3);
                int col = ks * 32 + ((lane >> 3) & 1) * 16;
                ldmatrix_x4(bf[np], bB + SWZ(row * 128 + col));
            }
#pragma unroll
            for (int mt = 0; mt < 4; mt++)
#pragma unroll
                for (int np = 0; np < 4; np++) {
                    mma16816h(c[mt][np * 2 + 0], af[mt], bf[np][0], bf[np][1]);
                    mma16816h(c[mt][np * 2 + 1], af[mt], bf[np][2], bf[np][3]);
                }
        }
    };

    load_stage(0);
    load_stage(1);
    for (int it = 0; it < NIT; ++it) {
        if (it == NIT - 1) asm volatile("cp.async.wait_group 0;" ::: "memory");
        else               asm volatile("cp.async.wait_group 1;" ::: "memory");
        __syncthreads();                 // stage it ready; buffer (it-1)%3 free
        if (it + 2 < NIT) load_stage(it + 2);
        compute_stage(it);
    }
    __syncthreads();   // all smem reads done; dynsmem reusable for staging

    // ---- Epilogue: per-warp stage (conflict-free) -> coalesced fp16 stores ----
    // Per warp: 64 rows x 272B ([128B hi | 128B lo] + 16B pad) = 17408B, 4 warps = 69.6KB.
    {
        char* stageW = dynsmem + warp * 17408;
        const int q = lane & 3;
#pragma unroll
        for (int mt = 0; mt < 4; mt++) {
#pragma unroll
            for (int h = 0; h < 2; h++) {
                int rloc = mt * 16 + h * 8 + (lane >> 2);       // 0..63
                int grow = o0 + wm * 64 + rloc;
                const float* bp = (grow < 256) ? bq : (grow < 512) ? bk : bv;
                float bias = bp[grow & 255];
                char* rowp = stageW + rloc * 272;
#pragma unroll
                for (int nt = 0; nt < 8; nt++) {
                    uint32_t hi, lo;
                    split_pair_h(c[mt][nt][h * 2 + 0] + bias,
                                 c[mt][nt][h * 2 + 1] + bias, hi, lo);
                    *(uint32_t*)(rowp + nt * 16 + q * 4)       = hi;
                    *(uint32_t*)(rowp + 128 + nt * 16 + q * 4) = lo;
                }
            }
        }
        __syncwarp();

        // Copy-out: 1024 x 16B chunks per warp; lo plane only for Q rows.
        unsigned char* outB = g_qkvs + (size_t)b * M3 * 16384;
        const int base_w = (p0 + wn * 64) * 2;   // byte offset within 8KB plane
#pragma unroll
        for (int i = 0; i < 32; i++) {
            int chunk  = i * 32 + lane;
            int rloc   = chunk >> 4;             // 0..63
            int within = chunk & 15;
            int plane  = within >> 3;            // 0=hi, 1=lo
            int col16  = within & 7;
            int grow = o0 + wm * 64 + rloc;
            if (plane == 0 || grow < 256) {
                uint4 v = *(uint4*)(stageW + rloc * 272 + within * 16);
                *(uint4*)(outB + (size_t)grow * 16384 + plane * 8192 + base_w + col16 * 16) = v;
            }
        }
    }
}

// ---------------------------------------------------------------------------
// Kernel D: attention on HMMA, fp16 2-term split (unchanged, round 12).
// S = (Qhi + Qlo) Khi^T;  ctx = (Phi + Plo) Vhi.
// smem: QHI QLO KHI VHI, 8KB each (32 KB total).
// ---------------------------------------------------------------------------
#define A_QHI 0
#define A_QLO 8192
#define A_KHI 16384
#define A_VHI 24576
#define ATTN_SMEM 32768

__global__ __launch_bounds__(128) void attn_kernel(float* __restrict__ out)
{
    const int t    = threadIdx.x;
    const int lane = t & 31;
    const int wy   = t >> 5;          // warp -> rows wy*16..wy*16+15

    const int blk = blockIdx.x;
    const int b   = blk >> 8;
    const int o   = blk & 255;

    const uint32_t sb = s2u(dynsmem);

    // ---- bulk copy with swizzle-on-destination ----
    const unsigned char* srcq = g_qkvs + (size_t)(b * M3 + o) * 16384;
#pragma unroll
    for (int i = 0; i < 16; i++) {
        int byteo = (t + i * 128) * 16;           // 0..32752
        size_t srco;
        if (byteo < 16384)      srco = (size_t)byteo;
        else if (byteo < 24576) srco = (size_t)256 * 16384 + (byteo - 16384);
        else                    srco = (size_t)512 * 16384 + (byteo - 24576);
        uint32_t dsto = (uint32_t)byteo ^ (((uint32_t)byteo >> 3) & 0x70);
        cp_async16(sb + dsto, srcq + srco);
    }
    asm volatile("cp.async.commit_group;");
    asm volatile("cp.async.wait_group 0;" ::: "memory");
    __syncthreads();

    // ---- S = Q Khi^T  (2 fp16 terms: Qhi + Qlo) ----
    float cS[8][4];
#pragma unroll
    for (int n = 0; n < 8; n++)
#pragma unroll
        for (int k = 0; k < 4; k++) cS[n][k] = 0.f;

#pragma unroll
    for (int ks = 0; ks < 4; ks++) {
        uint32_t ahi[4], alo[4];
        {
            int row = wy * 16 + (lane & 15);
            int col = ks * 32 + (lane >> 4) * 16;
            ldmatrix_x4(ahi, sb + A_QHI + SWZ(row * 128 + col));
            ldmatrix_x4(alo, sb + A_QLO + SWZ(row * 128 + col));
        }
#pragma unroll
        for (int np = 0; np < 4; np++) {
            uint32_t bhi[4];
            int row = np * 16 + (lane & 7) + ((lane >> 4) << 3);
            int col = ks * 32 + ((lane >> 3) & 1) * 16;
            ldmatrix_x4(bhi, sb + A_KHI + SWZ(row * 128 + col));
            mma16816h(cS[np * 2 + 0], ahi, bhi[0], bhi[1]);
            mma16816h(cS[np * 2 + 1], ahi, bhi[2], bhi[3]);
            mma16816h(cS[np * 2 + 0], alo, bhi[0], bhi[1]);
            mma16816h(cS[np * 2 + 1], alo, bhi[2], bhi[3]);
        }
    }

    // ---- softmax on fragments ----
    const float scale = 0.17677669529663687f;  // 1/sqrt(32)
    float m0 = -1e30f, m1 = -1e30f;
#pragma unroll
    for (int n = 0; n < 8; n++) {
#pragma unroll
        for (int k = 0; k < 4; k++) cS[n][k] *= scale;
        m0 = fmaxf(m0, fmaxf(cS[n][0], cS[n][1]));
        m1 = fmaxf(m1, fmaxf(cS[n][2], cS[n][3]));
    }
    m0 = fmaxf(m0, __shfl_xor_sync(0xffffffffu, m0, 1));
    m0 = fmaxf(m0, __shfl_xor_sync(0xffffffffu, m0, 2));
    m1 = fmaxf(m1, __shfl_xor_sync(0xffffffffu, m1, 1));
    m1 = fmaxf(m1, __shfl_xor_sync(0xffffffffu, m1, 2));

    float s0 = 0.f, s1 = 0.f;
#pragma unroll
    for (int n = 0; n < 8; n++) {
        cS[n][0] = __expf(cS[n][0] - m0);
        cS[n][1] = __expf(cS[n][1] - m0);
        cS[n][2] = __expf(cS[n][2] - m1);
        cS[n][3] = __expf(cS[n][3] - m1);
        s0 += cS[n][0] + cS[n][1];
        s1 += cS[n][2] + cS[n][3];
    }
    s0 += __shfl_xor_sync(0xffffffffu, s0, 1);
    s0 += __shfl_xor_sync(0xffffffffu, s0, 2);
    s1 += __shfl_xor_sync(0xffffffffu, s1, 1);
    s1 += __shfl_xor_sync(0xffffffffu, s1, 2);
    const float inv0 = 1.f / s0, inv1 = 1.f / s1;

    __syncthreads();   // all ldmatrix reads of q buffers done; safe to overwrite

    // ---- store P (fp16 hi/lo) into the q buffers, same A-operand layout ----
    {
        int r0 = wy * 16 + (lane >> 2);
        int col2 = (lane & 3) * 4;
#pragma unroll
        for (int n = 0; n < 8; n++) {
            float p0 = cS[n][0] * inv0, p1 = cS[n][1] * inv0;
            float p2 = cS[n][2] * inv1, p3 = cS[n][3] * inv1;
            uint32_t off0 = SWZ(r0 * 128 + n * 16 + col2);
            uint32_t off1 = SWZ((r0 + 8) * 128 + n * 16 + col2);
            uint32_t hi, lo;
            split_pair_h(p0, p1, hi, lo);
            *(uint32_t*)(dynsmem + A_QHI + off0) = hi;
            *(uint32_t*)(dynsmem + A_QLO + off0) = lo;
            split_pair_h(p2, p3, hi, lo);
            *(uint32_t*)(dynsmem + A_QHI + off1) = hi;
            *(uint32_t*)(dynsmem + A_QLO + off1) = lo;
        }
    }
    __syncthreads();

    // ---- ctx = P Vhi (2 fp16 terms); B via ldmatrix.trans on natural V ----
    float cC[8][4];
#pragma unroll
    for (int n = 0; n < 8; n++)
#pragma unroll
        for (int k = 0; k < 4; k++) cC[n][k] = 0.f;

#pragma unroll
    for (int ks = 0; ks < 4; ks++) {
        uint32_t ahi[4], alo[4];
        {
            int row = wy * 16 + (lane & 15);
            int col = ks * 32 + (lane >> 4) * 16;
            ldmatrix_x4(ahi, sb + A_QHI + SWZ(row * 128 + col));
            ldmatrix_x4(alo, sb + A_QLO + SWZ(row * 128 + col));
        }
#pragma unroll
        for (int np = 0; np < 4; np++) {
            uint32_t bhi[4];
            int row = ks * 16 + (lane & 7) + ((lane >> 3) & 1) * 8;
            int colb = np * 32 + (lane >> 4) * 16;
            ldmatrix_x4_trans(bhi, sb + A_VHI + SWZ(row * 128 + colb));
            mma16816h(cC[np * 2 + 0], ahi, bhi[0], bhi[1]);
            mma16816h(cC[np * 2 + 1], ahi, bhi[2], bhi[3]);
            mma16816h(cC[np * 2 + 0], alo, bhi[0], bhi[1]);
            mma16816h(cC[np * 2 + 1], alo, bhi[2], bhi[3]);
        }
    }

    // ---- epilogue ----
    float* op = out + ((size_t)b * 256 + o) * NPIX;
    int r0 = wy * 16 + (lane >> 2);
    int cb = (lane & 3) * 2;
#pragma unroll
    for (int n = 0; n < 8; n++) {
        *(float2*)(op + (size_t)r0 * 64 + n * 8 + cb)       = make_float2(cC[n][0], cC[n][1]);
        *(float2*)(op + (size_t)(r0 + 8) * 64 + n * 8 + cb) = make_float2(cC[n][2], cC[n][3]);
    }
}

extern "C" void kernel_launch(void* const* d_in, const int* in_sizes, int n_in,
                              void* d_out, int out_size)
{
    const float* x  = (const float*)d_in[0];
    const float* wq = (const float*)d_in[1];
    const float* bq = (const float*)d_in[2];
    const float* wk = (const float*)d_in[3];
    const float* bk = (const float*)d_in[4];
    const float* wv = (const float*)d_in[5];
    const float* bv = (const float*)d_in[6];
    float* out = (float*)d_out;

    cudaFuncSetAttribute(qkv_mma_kernel, cudaFuncAttributeMaxDynamicSharedMemorySize,
                         NSTAGE * STAGE_BYTES);
    cudaFuncSetAttribute(attn_kernel, cudaFuncAttributeMaxDynamicSharedMemorySize,
                         ATTN_SMEM);

    split_x_kernel<<<dim3(NPIX / 64, CIN / 64, BATCH), 256>>>(x);
    split_w_kernel<<<(M3 * CIN) / 256, 256>>>(wq, wk, wv);
    qkv_mma_kernel<<<dim3(NPIX / BN, M3 / BM, BATCH), 128, NSTAGE * STAGE_BYTES>>>(bq, bk, bv);
    attn_kernel<<<BATCH * 256, 128, ATTN_SMEM>>>(out);
}

// round 15
// speedup vs baseline: 1.5228x; 1.5228x over previous
#include <cuda_runtime.h>
#include <cuda_bf16.h>
#include <cuda_fp16.h>
#include <cstdint>

#define BATCH 16
#define CIN   256
#define NPIX  4096   // 64*64
#define M3    768    // combined q,k,v output channels
#define KX    256    // x storage k length (fp16 hi only)

// Scratch (device globals; no allocations allowed)
// g_qkvs: per (b, chan): [8KB fp16 hi plane | 8KB fp16 lo plane], NATURAL layout.
// lo planes are only written/read for the Q region (chan 0..255).
__device__ unsigned char g_qkvs[(size_t)BATCH * M3 * 16384];      // 201 MB
__device__ __half        g_xs [(size_t)BATCH * NPIX * KX];        // 34 MB  x fp16, [b][p][c]
__device__ __half        g_ws [(size_t)M3 * CIN];                 // 0.4 MB w_hi fp16, [o][c]

__device__ __forceinline__ uint32_t s2u(const void* p) {
    uint32_t a;
    asm("{ .reg .u64 t; cvta.to.shared.u64 t, %1; cvt.u32.u64 %0, t; }" : "=r"(a) : "l"(p));
    return a;
}

#define SWZ(off) ((off) ^ (((off) >> 3) & 0x70))

__device__ __forceinline__ void cp_async16(uint32_t dst, const void* src) {
    asm volatile("cp.async.cg.shared.global [%0], [%1], 16;" :: "r"(dst), "l"(src));
}

__device__ __forceinline__ void ldmatrix_x4(uint32_t* r, uint32_t addr) {
    asm volatile("ldmatrix.sync.aligned.m8n8.x4.shared.b16 {%0,%1,%2,%3}, [%4];"
                 : "=r"(r[0]), "=r"(r[1]), "=r"(r[2]), "=r"(r[3]) : "r"(addr));
}

__device__ __forceinline__ void ldmatrix_x4_trans(uint32_t* r, uint32_t addr) {
    asm volatile("ldmatrix.sync.aligned.m8n8.x4.trans.shared.b16 {%0,%1,%2,%3}, [%4];"
                 : "=r"(r[0]), "=r"(r[1]), "=r"(r[2]), "=r"(r[3]) : "r"(addr));
}

// fp16 mma
__device__ __forceinline__ void mma16816h(float* c, const uint32_t* a, uint32_t b0, uint32_t b1) {
    asm volatile(
        "mma.sync.aligned.m16n8k16.row.col.f32.f16.f16.f32 "
        "{%0,%1,%2,%3}, {%4,%5,%6,%7}, {%8,%9}, {%0,%1,%2,%3};"
        : "+f"(c[0]), "+f"(c[1]), "+f"(c[2]), "+f"(c[3])
        : "r"(a[0]), "r"(a[1]), "r"(a[2]), "r"(a[3]), "r"(b0), "r"(b1));
}

// Split v0,v1 into hi/lo fp16 pairs.
__device__ __forceinline__ void split_pair_h(float v0, float v1, uint32_t& hi, uint32_t& lo) {
    __half h0 = __float2half(v0);
    __half h1 = __float2half(v1);
    __half2 H; H.x = h0; H.y = h1;
    __half2 L;
    L.x = __float2half(v0 - __half2float(h0));
    L.y = __float2half(v1 - __half2float(h1));
    hi = *(uint32_t*)&H;
    lo = *(uint32_t*)&L;
}

// ---------------------------------------------------------------------------
// Kernel A: x -> fp16, transposed to [b][p][c]
// ---------------------------------------------------------------------------
__global__ __launch_bounds__(256) void split_x_kernel(const float* __restrict__ x) {
    __shared__ float s[64][65];
    const int b = blockIdx.z, c0 = blockIdx.y * 64, p0 = blockIdx.x * 64;
    const float* xb = x + ((size_t)b * CIN + c0) * NPIX + p0;
    const int t = threadIdx.x;
#pragma unroll
    for (int i = 0; i < 16; i++) {
        int idx = t + 256 * i;
        int c = idx >> 6, p = idx & 63;
        s[c][p] = xb[(size_t)c * NPIX + p];
    }
    __syncthreads();
    __half* xs = g_xs + ((size_t)b * NPIX + p0) * KX + c0;
#pragma unroll
    for (int i = 0; i < 16; i++) {
        int idx = t + 256 * i;
        int cc = idx & 63, p = idx >> 6;
        xs[(size_t)p * KX + cc] = __float2half(s[cc][p]);
    }
}

// ---------------------------------------------------------------------------
// Kernel B: w_hi fp16, [o][c]
// ---------------------------------------------------------------------------
__global__ __launch_bounds__(256) void split_w_kernel(
    const float* __restrict__ wq, const float* __restrict__ wk, const float* __restrict__ wv) {
    int idx = blockIdx.x * 256 + threadIdx.x;   // 768*256 total
    int o = idx >> 8, c = idx & 255;
    const float* w = (o < 256) ? wq : (o < 512) ? wk : wv;
    g_ws[idx] = __float2half(w[(o & 255) * CIN + c]);
}

// ---------------------------------------------------------------------------
// Kernel C: HMMA fp16 GEMM, K'=256 (plain fp16), r12-proven config:
// tile 128x128, 256 threads (4x2 warps, warp tile 32x64), 3-stage cp.async.
// ---------------------------------------------------------------------------
#define BM 128
#define BN 128
#define BK 64
#define NIT 4
#define STAGE_BYTES (BM * BK * 2 + BN * BK * 2)   // 32 KB (A then B)
#define NSTAGE 3

extern __shared__ __align__(1024) char dynsmem[];

__global__ __launch_bounds__(256, 2) void qkv_mma_kernel(
    const float* __restrict__ bq, const float* __restrict__ bk, const float* __restrict__ bv)
{
    const int t    = threadIdx.x;
    const int lane = t & 31;
    const int warp = t >> 5;
    const int wm   = warp & 3;     // 4 warps along M: 32 rows each
    const int wn   = warp >> 2;    // 2 warps along N: 64 cols each

    const int b  = blockIdx.z;
    const int o0 = blockIdx.y * BM;
    const int p0 = blockIdx.x * BN;

    const uint32_t smemBase = s2u(dynsmem);

    const __half* Wb = g_ws + (size_t)o0 * CIN;
    const __half* Xb = g_xs + ((size_t)b * NPIX + p0) * KX;

    float c[2][8][4];
#pragma unroll
    for (int i = 0; i < 2; i++)
#pragma unroll
        for (int j = 0; j < 8; j++)
#pragma unroll
            for (int k = 0; k < 4; k++) c[i][j][k] = 0.f;

    auto load_stage = [&](int it) {
        const int kk = it * BK;                // 0..192: straight through K=256
        const uint32_t aB = smemBase + (it % NSTAGE) * STAGE_BYTES;
        const uint32_t bB = aB + BM * BK * 2;
#pragma unroll
        for (int j = 0; j < 4; j++) {
            int idx = t + 256 * j;
            int row = idx >> 3, c16 = idx & 7;
            cp_async16(aB + SWZ(row * 128 + c16 * 16),
                       (const char*)(Wb + (size_t)row * CIN + kk) + c16 * 16);
        }
#pragma unroll
        for (int j = 0; j < 4; j++) {
            int idx = t + 256 * j;
            int row = idx >> 3, c16 = idx & 7;
            cp_async16(bB + SWZ(row * 128 + c16 * 16),
                       (const char*)(Xb + (size_t)row * KX + kk) + c16 * 16);
        }
        asm volatile("cp.async.commit_group;");
    };

    auto compute_stage = [&](int it) {
        const uint32_t aB = smemBase + (it % NSTAGE) * STAGE_BYTES;
        const uint32_t bB = aB + BM * BK * 2;
#pragma unroll
        for (int ks = 0; ks < 4; ks++) {
            uint32_t af[2][4];
#pragma unroll
            for (int mt = 0; mt < 2; mt++) {
                int row = wm * 32 + mt * 16 + (lane & 15);
                int col = ks * 32 + (lane >> 4) * 16;
                ldmatrix_x4(af[mt], aB + SWZ(row * 128 + col));
            }
            uint32_t bf[4][4];
#pragma unroll
            for (int np = 0; np < 4; np++) {
                int row = wn * 64 + np * 16 + (lane & 7) + ((lane >> 4) << 3);
                int col = ks * 32 + ((lane >> 3) & 1) * 16;
                ldmatrix_x4(bf[np], bB + SWZ(row * 128 + col));
            }
#pragma unroll
            for (int mt = 0; mt < 2; mt++)
#pragma unroll
                for (int np = 0; np < 4; np++) {
                    mma16816h(c[mt][np * 2 + 0], af[mt], bf[np][0], bf[np][1]);
                    mma16816h(c[mt][np * 2 + 1], af[mt], bf[np][2], bf[np][3]);
                }
        }
    };

    load_stage(0);
    load_stage(1);
    for (int it = 0; it < NIT; ++it) {
        if (it == NIT - 1) asm volatile("cp.async.wait_group 0;" ::: "memory");
        else               asm volatile("cp.async.wait_group 1;" ::: "memory");
        __syncthreads();                 // stage it ready; buffer (it-1)%3 free
        if (it + 2 < NIT) load_stage(it + 2);
        compute_stage(it);
    }
    __syncthreads();   // all smem reads done; dynsmem reusable for staging

    // ---- Epilogue: per-warp stage (conflict-free) -> coalesced fp16 stores ----
    {
        char* stageW = dynsmem + warp * 8704;    // 8 warps * 8704 = 69632 <= 96KB
        const int q = lane & 3;
#pragma unroll
        for (int mt = 0; mt < 2; mt++) {
#pragma unroll
            for (int h = 0; h < 2; h++) {
                int rloc = mt * 16 + h * 8 + (lane >> 2);
                int grow = o0 + wm * 32 + rloc;
                const float* bp = (grow < 256) ? bq : (grow < 512) ? bk : bv;
                float bias = bp[grow & 255];
                char* rowp = stageW + rloc * 272;
#pragma unroll
                for (int nt = 0; nt < 8; nt++) {
                    uint32_t hi, lo;
                    split_pair_h(c[mt][nt][h * 2 + 0] + bias,
                                 c[mt][nt][h * 2 + 1] + bias, hi, lo);
                    *(uint32_t*)(rowp + nt * 16 + q * 4)       = hi;
                    *(uint32_t*)(rowp + 128 + nt * 16 + q * 4) = lo;
                }
            }
        }
        __syncwarp();

        // Copy-out: lo plane only for Q rows (grow < 256).
        unsigned char* outB = g_qkvs + (size_t)b * M3 * 16384;
        const int base_w = (p0 + wn * 64) * 2;   // byte offset within 8KB plane
#pragma unroll
        for (int i = 0; i < 16; i++) {
            int chunk  = i * 32 + lane;
            int rloc   = chunk >> 4;
            int within = chunk & 15;
            int plane  = within >> 3;            // 0=hi, 1=lo
            int col16  = within & 7;
            int grow = o0 + wm * 32 + rloc;
            if (plane == 0 || grow < 256) {
                uint4 v = *(uint4*)(stageW + rloc * 272 + within * 16);
                *(uint4*)(outB + (size_t)grow * 16384 + plane * 8192 + base_w + col16 * 16) = v;
            }
        }
    }
}

// ---------------------------------------------------------------------------
// Kernel D: attention on HMMA, fp16 2-term split (unchanged, round 12).
// S = (Qhi + Qlo) Khi^T;  ctx = (Phi + Plo) Vhi.
// smem: QHI QLO KHI VHI, 8KB each (32 KB total).
// ---------------------------------------------------------------------------
#define A_QHI 0
#define A_QLO 8192
#define A_KHI 16384
#define A_VHI 24576
#define ATTN_SMEM 32768

__global__ __launch_bounds__(128) void attn_kernel(float* __restrict__ out)
{
    const int t    = threadIdx.x;
    const int lane = t & 31;
    const int wy   = t >> 5;          // warp -> rows wy*16..wy*16+15

    const int blk = blockIdx.x;
    const int b   = blk >> 8;
    const int o   = blk & 255;

    const uint32_t sb = s2u(dynsmem);

    // ---- bulk copy with swizzle-on-destination ----
    const unsigned char* srcq = g_qkvs + (size_t)(b * M3 + o) * 16384;
#pragma unroll
    for (int i = 0; i < 16; i++) {
        int byteo = (t + i * 128) * 16;           // 0..32752
        size_t srco;
        if (byteo < 16384)      srco = (size_t)byteo;
        else if (byteo < 24576) srco = (size_t)256 * 16384 + (byteo - 16384);
        else                    srco = (size_t)512 * 16384 + (byteo - 24576);
        uint32_t dsto = (uint32_t)byteo ^ (((uint32_t)byteo >> 3) & 0x70);
        cp_async16(sb + dsto, srcq + srco);
    }
    asm volatile("cp.async.commit_group;");
    asm volatile("cp.async.wait_group 0;" ::: "memory");
    __syncthreads();

    // ---- S = Q Khi^T  (2 fp16 terms: Qhi + Qlo) ----
    float cS[8][4];
#pragma unroll
    for (int n = 0; n < 8; n++)
#pragma unroll
        for (int k = 0; k < 4; k++) cS[n][k] = 0.f;

#pragma unroll
    for (int ks = 0; ks < 4; ks++) {
        uint32_t ahi[4], alo[4];
        {
            int row = wy * 16 + (lane & 15);
            int col = ks * 32 + (lane >> 4) * 16;
            ldmatrix_x4(ahi, sb + A_QHI + SWZ(row * 128 + col));
            ldmatrix_x4(alo, sb + A_QLO + SWZ(row * 128 + col));
        }
#pragma unroll
        for (int np = 0; np < 4; np++) {
            uint32_t bhi[4];
            int row = np * 16 + (lane & 7) + ((lane >> 4) << 3);
            int col = ks * 32 + ((lane >> 3) & 1) * 16;
            ldmatrix_x4(bhi, sb + A_KHI + SWZ(row * 128 + col));
            mma16816h(cS[np * 2 + 0], ahi, bhi[0], bhi[1]);
            mma16816h(cS[np * 2 + 1], ahi, bhi[2], bhi[3]);
            mma16816h(cS[np * 2 + 0], alo, bhi[0], bhi[1]);
            mma16816h(cS[np * 2 + 1], alo, bhi[2], bhi[3]);
        }
    }

    // ---- softmax on fragments ----
    const float scale = 0.17677669529663687f;  // 1/sqrt(32)
    float m0 = -1e30f, m1 = -1e30f;
#pragma unroll
    for (int n = 0; n < 8; n++) {
#pragma unroll
        for (int k = 0; k < 4; k++) cS[n][k] *= scale;
        m0 = fmaxf(m0, fmaxf(cS[n][0], cS[n][1]));
        m1 = fmaxf(m1, fmaxf(cS[n][2], cS[n][3]));
    }
    m0 = fmaxf(m0, __shfl_xor_sync(0xffffffffu, m0, 1));
    m0 = fmaxf(m0, __shfl_xor_sync(0xffffffffu, m0, 2));
    m1 = fmaxf(m1, __shfl_xor_sync(0xffffffffu, m1, 1));
    m1 = fmaxf(m1, __shfl_xor_sync(0xffffffffu, m1, 2));

    float s0 = 0.f, s1 = 0.f;
#pragma unroll
    for (int n = 0; n < 8; n++) {
        cS[n][0] = __expf(cS[n][0] - m0);
        cS[n][1] = __expf(cS[n][1] - m0);
        cS[n][2] = __expf(cS[n][2] - m1);
        cS[n][3] = __expf(cS[n][3] - m1);
        s0 += cS[n][0] + cS[n][1];
        s1 += cS[n][2] + cS[n][3];
    }
    s0 += __shfl_xor_sync(0xffffffffu, s0, 1);
    s0 += __shfl_xor_sync(0xffffffffu, s0, 2);
    s1 += __shfl_xor_sync(0xffffffffu, s1, 1);
    s1 += __shfl_xor_sync(0xffffffffu, s1, 2);
    const float inv0 = 1.f / s0, inv1 = 1.f / s1;

    __syncthreads();   // all ldmatrix reads of q buffers done; safe to overwrite

    // ---- store P (fp16 hi/lo) into the q buffers, same A-operand layout ----
    {
        int r0 = wy * 16 + (lane >> 2);
        int col2 = (lane & 3) * 4;
#pragma unroll
        for (int n = 0; n < 8; n++) {
            float p0 = cS[n][0] * inv0, p1 = cS[n][1] * inv0;
            float p2 = cS[n][2] * inv1, p3 = cS[n][3] * inv1;
            uint32_t off0 = SWZ(r0 * 128 + n * 16 + col2);
            uint32_t off1 = SWZ((r0 + 8) * 128 + n * 16 + col2);
            uint32_t hi, lo;
            split_pair_h(p0, p1, hi, lo);
            *(uint32_t*)(dynsmem + A_QHI + off0) = hi;
            *(uint32_t*)(dynsmem + A_QLO + off0) = lo;
            split_pair_h(p2, p3, hi, lo);
            *(uint32_t*)(dynsmem + A_QHI + off1) = hi;
            *(uint32_t*)(dynsmem + A_QLO + off1) = lo;
        }
    }
    __syncthreads();

    // ---- ctx = P Vhi (2 fp16 terms); B via ldmatrix.trans on natural V ----
    float cC[8][4];
#pragma unroll
    for (int n = 0; n < 8; n++)
#pragma unroll
        for (int k = 0; k < 4; k++) cC[n][k] = 0.f;

#pragma unroll
    for (int ks = 0; ks < 4; ks++) {
        uint32_t ahi[4], alo[4];
        {
            int row = wy * 16 + (lane & 15);
            int col = ks * 32 + (lane >> 4) * 16;
            ldmatrix_x4(ahi, sb + A_QHI + SWZ(row * 128 + col));
            ldmatrix_x4(alo, sb + A_QLO + SWZ(row * 128 + col));
        }
#pragma unroll
        for (int np = 0; np < 4; np++) {
            uint32_t bhi[4];
            int row = ks * 16 + (lane & 7) + ((lane >> 3) & 1) * 8;
            int colb = np * 32 + (lane >> 4) * 16;
            ldmatrix_x4_trans(bhi, sb + A_VHI + SWZ(row * 128 + colb));
            mma16816h(cC[np * 2 + 0], ahi, bhi[0], bhi[1]);
            mma16816h(cC[np * 2 + 1], ahi, bhi[2], bhi[3]);
            mma16816h(cC[np * 2 + 0], alo, bhi[0], bhi[1]);
            mma16816h(cC[np * 2 + 1], alo, bhi[2], bhi[3]);
        }
    }

    // ---- epilogue ----
    float* op = out + ((size_t)b * 256 + o) * NPIX;
    int r0 = wy * 16 + (lane >> 2);
    int cb = (lane & 3) * 2;
#pragma unroll
    for (int n = 0; n < 8; n++) {
        *(float2*)(op + (size_t)r0 * 64 + n * 8 + cb)       = make_float2(cC[n][0], cC[n][1]);
        *(float2*)(op + (size_t)(r0 + 8) * 64 + n * 8 + cb) = make_float2(cC[n][2], cC[n][3]);
    }
}

extern "C" void kernel_launch(void* const* d_in, const int* in_sizes, int n_in,
                              void* d_out, int out_size)
{
    const float* x  = (const float*)d_in[0];
    const float* wq = (const float*)d_in[1];
    const float* bq = (const float*)d_in[2];
    const float* wk = (const float*)d_in[3];
    const float* bk = (const float*)d_in[4];
    const float* wv = (const float*)d_in[5];
    const float* bv = (const float*)d_in[6];
    float* out = (float*)d_out;

    cudaFuncSetAttribute(qkv_mma_kernel, cudaFuncAttributeMaxDynamicSharedMemorySize,
                         NSTAGE * STAGE_BYTES);
    cudaFuncSetAttribute(attn_kernel, cudaFuncAttributeMaxDynamicSharedMemorySize,
                         ATTN_SMEM);

    split_x_kernel<<<dim3(NPIX / 64, CIN / 64, BATCH), 256>>>(x);
    split_w_kernel<<<(M3 * CIN) / 256, 256>>>(wq, wk, wv);
    qkv_mma_kernel<<<dim3(NPIX / BN, M3 / BM, BATCH), 256, NSTAGE * STAGE_BYTES>>>(bq, bk, bv);
    attn_kernel<<<BATCH * 256, 128, ATTN_SMEM>>>(out);
}